// round 1
// baseline (speedup 1.0000x reference)
#include <cuda_runtime.h>

// Problem constants (fixed by setup_inputs)
#define Bb 8
#define Cc 64
#define Nn 4096
#define Ee 8
#define KSPLIT 8          // key-dimension splits for parallelism
#define KEYS_PER_SPLIT (Nn / KSPLIT)   // 512
#define QT_PER_CTA 512    // 128 threads * 4 queries
#define BCN ((size_t)Bb * Cc * Nn)

// Scratch (allocation-free rule: __device__ globals)
// fh: per (b,n): f0,f0,f1,f1,...,f7,f7, h0,h0,...,h7,h7  (duplicated for f32x2)
__device__ float d_fh[Bb * Nn * 32];          // 4 MB
__device__ float d_g [Bb * Nn * 8];           // 1 MB
__device__ float d_part[KSPLIT * Bb * Nn * 9];// 9.4 MB: acc[8] + den per (split,b,m)

// ---------------- f32x2 helpers (Blackwell packed fp32) ----------------
__device__ __forceinline__ unsigned long long ffma2(unsigned long long a,
                                                    unsigned long long b,
                                                    unsigned long long c) {
    unsigned long long d;
    asm("fma.rn.f32x2 %0, %1, %2, %3;" : "=l"(d) : "l"(a), "l"(b), "l"(c));
    return d;
}
__device__ __forceinline__ unsigned long long fadd2(unsigned long long a,
                                                    unsigned long long b) {
    unsigned long long d;
    asm("add.rn.f32x2 %0, %1, %2;" : "=l"(d) : "l"(a), "l"(b));
    return d;
}
__device__ __forceinline__ unsigned long long pk2(float lo, float hi) {
    unsigned long long r;
    asm("mov.b64 %0, {%1, %2};" : "=l"(r) : "f"(lo), "f"(hi));
    return r;
}
__device__ __forceinline__ void upk2(unsigned long long v, float& lo, float& hi) {
    asm("mov.b64 {%0, %1}, %2;" : "=f"(lo), "=f"(hi) : "l"(v));
}

// ---------------- Kernel A: 1x1-conv projections f, g, h ----------------
// grid (Nn/128, Bb), block 128. Each thread owns one pixel n.
__global__ __launch_bounds__(128) void proj_kernel(
    const float* __restrict__ x,
    const float* __restrict__ Wk, const float* __restrict__ bk,
    const float* __restrict__ Wq, const float* __restrict__ bq,
    const float* __restrict__ Wv, const float* __restrict__ bv)
{
    __shared__ __align__(16) float xs[64 * 128];
    __shared__ float wks[512], wqs[512], wvs[512];
    __shared__ float bks[8], bqs[8], bvs[8];
    const int t  = threadIdx.x;
    const int b  = blockIdx.y;
    const int n0 = blockIdx.x * 128;

    for (int i = t; i < 512; i += 128) { wks[i] = Wk[i]; wqs[i] = Wq[i]; wvs[i] = Wv[i]; }
    if (t < 8) { bks[t] = bk[t]; bqs[t] = bq[t]; bvs[t] = bv[t]; }
    #pragma unroll 8
    for (int c = 0; c < 64; c++)
        xs[c * 128 + t] = x[((size_t)b * 64 + c) * Nn + n0 + t];
    __syncthreads();

    float f[8], g[8], h[8];
    #pragma unroll
    for (int e = 0; e < 8; e++) { f[e] = bks[e]; g[e] = bqs[e]; h[e] = bvs[e]; }

    #pragma unroll 4
    for (int c = 0; c < 64; c++) {
        const float xv = xs[c * 128 + t];
        #pragma unroll
        for (int e = 0; e < 8; e++) {
            f[e] = fmaf(wks[e * 64 + c], xv, f[e]);
            g[e] = fmaf(wqs[e * 64 + c], xv, g[e]);
            h[e] = fmaf(wvs[e * 64 + c], xv, h[e]);
        }
    }

    const int n = n0 + t;
    float4* fhp = (float4*)&d_fh[(size_t)(b * Nn + n) * 32];
    #pragma unroll
    for (int j = 0; j < 4; j++)
        fhp[j]     = make_float4(f[2*j], f[2*j], f[2*j+1], f[2*j+1]);
    #pragma unroll
    for (int j = 0; j < 4; j++)
        fhp[4 + j] = make_float4(h[2*j], h[2*j], h[2*j+1], h[2*j+1]);
    float4* gp = (float4*)&d_g[(size_t)(b * Nn + n) * 8];
    gp[0] = make_float4(g[0], g[1], g[2], g[3]);
    gp[1] = make_float4(g[4], g[5], g[6], g[7]);
}

// ---------------- Kernel B: fused attention core (split-K over keys) ----
// grid (KSPLIT, Nn/QT_PER_CTA, Bb), block 128. Thread owns 4 queries (2 f32x2 pairs).
__global__ __launch_bounds__(128) void attn_kernel()
{
    __shared__ __align__(16) float sm[128 * 32];   // 128-key tile, duplicated f|h
    const int t  = threadIdx.x;
    const int ks = blockIdx.x;
    const int qt = blockIdx.y;
    const int b  = blockIdx.z;
    const int m0 = qt * QT_PER_CTA + t * 4;

    // Query vectors: pairs (m0,m0+1) and (m0+2,m0+3)
    unsigned long long g2[2][8];
    {
        const float* gp = &d_g[(size_t)(b * Nn + m0) * 8];
        #pragma unroll
        for (int p = 0; p < 2; p++)
            #pragma unroll
            for (int e = 0; e < 8; e++)
                g2[p][e] = pk2(gp[(2 * p) * 8 + e], gp[(2 * p + 1) * 8 + e]);
    }

    unsigned long long acc2[2][8];
    unsigned long long den2[2];
    #pragma unroll
    for (int p = 0; p < 2; p++) {
        den2[p] = 0ull;
        #pragma unroll
        for (int e = 0; e < 8; e++) acc2[p][e] = 0ull;
    }

    const int kbase = ks * KEYS_PER_SPLIT;
    for (int kt = 0; kt < KEYS_PER_SPLIT; kt += 128) {
        // Stage 128 keys (128B each) into shared
        const float4* src = (const float4*)&d_fh[(size_t)(b * Nn + kbase + kt) * 32];
        float4* dst = (float4*)sm;
        #pragma unroll
        for (int j = 0; j < 8; j++) dst[t * 8 + j] = src[t * 8 + j];
        __syncthreads();

        #pragma unroll 2
        for (int k = 0; k < 128; k++) {
            const ulonglong2* row = (const ulonglong2*)&sm[k * 32];
            unsigned long long s20 = 0ull, s21 = 0ull;
            #pragma unroll
            for (int j = 0; j < 4; j++) {
                const ulonglong2 fv = row[j];            // (f2j dup, f2j+1 dup)
                s20 = ffma2(fv.x, g2[0][2*j],     s20);
                s21 = ffma2(fv.x, g2[1][2*j],     s21);
                s20 = ffma2(fv.y, g2[0][2*j + 1], s20);
                s21 = ffma2(fv.y, g2[1][2*j + 1], s21);
            }
            float s0, s1, s2, s3;
            upk2(s20, s0, s1); upk2(s21, s2, s3);
            const float p0 = __expf(s0), p1 = __expf(s1);
            const float p2 = __expf(s2), p3 = __expf(s3);
            const unsigned long long p20 = pk2(p0, p1), p21 = pk2(p2, p3);
            den2[0] = fadd2(den2[0], p20);
            den2[1] = fadd2(den2[1], p21);
            #pragma unroll
            for (int j = 0; j < 4; j++) {
                const ulonglong2 hv = row[4 + j];        // (h2j dup, h2j+1 dup)
                acc2[0][2*j]     = ffma2(hv.x, p20, acc2[0][2*j]);
                acc2[1][2*j]     = ffma2(hv.x, p21, acc2[1][2*j]);
                acc2[0][2*j + 1] = ffma2(hv.y, p20, acc2[0][2*j + 1]);
                acc2[1][2*j + 1] = ffma2(hv.y, p21, acc2[1][2*j + 1]);
            }
        }
        __syncthreads();
    }

    // Write partials: acc[8] + den per query
    #pragma unroll
    for (int p = 0; p < 2; p++) {
        float lo[9], hi[9];
        #pragma unroll
        for (int e = 0; e < 8; e++) upk2(acc2[p][e], lo[e], hi[e]);
        upk2(den2[p], lo[8], hi[8]);
        const int mA = m0 + 2 * p, mB = mA + 1;
        float* outA = &d_part[(((size_t)ks * Bb + b) * Nn + mA) * 9];
        float* outB = &d_part[(((size_t)ks * Bb + b) * Nn + mB) * 9];
        #pragma unroll
        for (int e = 0; e < 9; e++) { outA[e] = lo[e]; outB[e] = hi[e]; }
    }
}

// ---------------- Kernel C: combine splits, Wo projection, y/gamma ------
// grid (Nn/128, Bb), block 128.
__global__ __launch_bounds__(128) void out_kernel(
    const float* __restrict__ x,
    const float* __restrict__ Wo, const float* __restrict__ bo,
    const float* __restrict__ gamma, float* __restrict__ out)
{
    __shared__ float vs[8 * 128];
    __shared__ float wos[512], bos[64];
    const int t  = threadIdx.x;
    const int b  = blockIdx.y;
    const int m  = blockIdx.x * 128 + t;

    for (int i = t; i < 512; i += 128) wos[i] = Wo[i];
    if (t < 64) bos[t] = bo[t];

    float acc[8] = {0,0,0,0,0,0,0,0};
    float den = 0.0f;
    #pragma unroll
    for (int s = 0; s < KSPLIT; s++) {
        const float* pp = &d_part[(((size_t)s * Bb + b) * Nn + m) * 9];
        #pragma unroll
        for (int e = 0; e < 8; e++) acc[e] += pp[e];
        den += pp[8];
    }
    const float inv = 1.0f / den;
    #pragma unroll
    for (int e = 0; e < 8; e++) vs[e * 128 + t] = acc[e] * inv;
    __syncthreads();

    const float gam = gamma[0];
    #pragma unroll 4
    for (int c = 0; c < 64; c++) {
        float o = bos[c];
        #pragma unroll
        for (int e = 0; e < 8; e++) o = fmaf(wos[c * 8 + e], vs[e * 128 + t], o);
        const size_t idx = ((size_t)b * 64 + c) * Nn + m;
        out[BCN + idx] = o;                    // o
        out[idx]       = fmaf(gam, o, x[idx]); // y = gamma*o + x
    }
    if (b == 0 && m == 0) out[2 * BCN] = gam;  // gamma scalar
}

// ---------------- Launch -------------------------------------------------
extern "C" void kernel_launch(void* const* d_in, const int* in_sizes, int n_in,
                              void* d_out, int out_size)
{
    const float* x     = (const float*)d_in[0];
    const float* Wk    = (const float*)d_in[1];
    const float* bk    = (const float*)d_in[2];
    const float* Wq    = (const float*)d_in[3];
    const float* bq    = (const float*)d_in[4];
    const float* Wv    = (const float*)d_in[5];
    const float* bv    = (const float*)d_in[6];
    const float* Wo    = (const float*)d_in[7];
    const float* bo    = (const float*)d_in[8];
    const float* gamma = (const float*)d_in[9];
    float* out = (float*)d_out;

    proj_kernel<<<dim3(Nn / 128, Bb), 128>>>(x, Wk, bk, Wq, bq, Wv, bv);
    attn_kernel<<<dim3(KSPLIT, Nn / QT_PER_CTA, Bb), 128>>>();
    out_kernel<<<dim3(Nn / 128, Bb), 128>>>(x, Wo, bo, gamma, out);
}

// round 2
// speedup vs baseline: 2.1626x; 2.1626x over previous
#include <cuda_runtime.h>

// Problem constants (fixed by setup_inputs)
#define Bb 8
#define Cc 64
#define Nn 4096
#define Ee 8
#define KSPLIT 16                      // key-dimension splits
#define KEYS (Nn / KSPLIT)             // 256 keys per split
#define QT_PER_CTA 512                 // 128 threads * 4 queries
#define BCN ((size_t)Bb * Cc * Nn)
#define LOG2E 1.4426950408889634f

// Scratch (__device__ globals per allocation-free rule)
// fh per (b,n): f0,f0,f1,f1,...,f7,f7, h0,h0,...,h7,h7 (dup for f32x2)
__device__ float d_fh[Bb * Nn * 32];                   // 4 MB
__device__ float d_g [Bb * Nn * 8];                    // 1 MB  (pre-scaled by log2e)
__device__ float d_pacc[(size_t)KSPLIT * Bb * Nn * 8]; // 16.8 MB
__device__ float d_pden[(size_t)KSPLIT * Bb * Nn];     // 2.1 MB

// ---------------- f32x2 + ex2 helpers ----------------
__device__ __forceinline__ unsigned long long ffma2(unsigned long long a,
                                                    unsigned long long b,
                                                    unsigned long long c) {
    unsigned long long d;
    asm("fma.rn.f32x2 %0, %1, %2, %3;" : "=l"(d) : "l"(a), "l"(b), "l"(c));
    return d;
}
__device__ __forceinline__ unsigned long long fadd2(unsigned long long a,
                                                    unsigned long long b) {
    unsigned long long d;
    asm("add.rn.f32x2 %0, %1, %2;" : "=l"(d) : "l"(a), "l"(b));
    return d;
}
__device__ __forceinline__ unsigned long long pk2(float lo, float hi) {
    unsigned long long r;
    asm("mov.b64 %0, {%1, %2};" : "=l"(r) : "f"(lo), "f"(hi));
    return r;
}
__device__ __forceinline__ void upk2(unsigned long long v, float& lo, float& hi) {
    asm("mov.b64 {%0, %1}, %2;" : "=f"(lo), "=f"(hi) : "l"(v));
}
__device__ __forceinline__ float ex2f(float x) {
    float y;
    asm("ex2.approx.f32 %0, %1;" : "=f"(y) : "f"(x));
    return y;
}

// ---------------- Kernel A: projections f, g, h --------------------------
// grid (Nn/128, Bb), block 128. One pixel per thread, x read directly (coalesced).
__global__ __launch_bounds__(128) void proj_kernel(
    const float* __restrict__ x,
    const float* __restrict__ Wk, const float* __restrict__ bk,
    const float* __restrict__ Wq, const float* __restrict__ bq,
    const float* __restrict__ Wv, const float* __restrict__ bv)
{
    __shared__ float wks[512], wqs[512], wvs[512];
    __shared__ float bks[8], bqs[8], bvs[8];
    const int t  = threadIdx.x;
    const int b  = blockIdx.y;
    const int n  = blockIdx.x * 128 + t;

    for (int i = t; i < 512; i += 128) {
        wks[i] = Wk[i];
        wqs[i] = Wq[i] * LOG2E;   // fold log2e into query path
        wvs[i] = Wv[i];
    }
    if (t < 8) { bks[t] = bk[t]; bqs[t] = bq[t] * LOG2E; bvs[t] = bv[t]; }
    __syncthreads();

    float f[8], g[8], h[8];
    #pragma unroll
    for (int e = 0; e < 8; e++) { f[e] = bks[e]; g[e] = bqs[e]; h[e] = bvs[e]; }

    const float* xp = &x[(size_t)b * 64 * Nn + n];
    #pragma unroll 8
    for (int c = 0; c < 64; c++) {
        const float xv = xp[(size_t)c * Nn];
        #pragma unroll
        for (int e = 0; e < 8; e++) {
            f[e] = fmaf(wks[e * 64 + c], xv, f[e]);
            g[e] = fmaf(wqs[e * 64 + c], xv, g[e]);
            h[e] = fmaf(wvs[e * 64 + c], xv, h[e]);
        }
    }

    float4* fhp = (float4*)&d_fh[(size_t)(b * Nn + n) * 32];
    #pragma unroll
    for (int j = 0; j < 4; j++)
        fhp[j]     = make_float4(f[2*j], f[2*j], f[2*j+1], f[2*j+1]);
    #pragma unroll
    for (int j = 0; j < 4; j++)
        fhp[4 + j] = make_float4(h[2*j], h[2*j], h[2*j+1], h[2*j+1]);
    float4* gp = (float4*)&d_g[(size_t)(b * Nn + n) * 8];
    gp[0] = make_float4(g[0], g[1], g[2], g[3]);
    gp[1] = make_float4(g[4], g[5], g[6], g[7]);
}

// ---------------- Kernel B: fused attention core (split-K) ---------------
// grid (KSPLIT, Nn/QT_PER_CTA, Bb), block 128. Thread owns 4 queries (2 f32x2).
// Whole 256-key split staged in smem once; sync-free unrolled main loop.
__global__ __launch_bounds__(128, 3) void attn_kernel()
{
    __shared__ __align__(16) float sm[KEYS * 32];      // 32 KB
    const int t  = threadIdx.x;
    const int ks = blockIdx.x;
    const int qt = blockIdx.y;
    const int b  = blockIdx.z;
    const int m0 = qt * QT_PER_CTA + t * 4;

    // Stage all keys for this split: 2048 float4, 16 per thread (coalesced)
    {
        const float4* src = (const float4*)&d_fh[(size_t)(b * Nn + ks * KEYS) * 32];
        float4* dst = (float4*)sm;
        #pragma unroll
        for (int j = 0; j < 16; j++) dst[j * 128 + t] = src[j * 128 + t];
    }

    // Query vectors (already scaled by log2e): pairs (m0,m0+1),(m0+2,m0+3)
    unsigned long long g2[2][8];
    {
        const float* gp = &d_g[(size_t)(b * Nn + m0) * 8];
        #pragma unroll
        for (int p = 0; p < 2; p++)
            #pragma unroll
            for (int e = 0; e < 8; e++)
                g2[p][e] = pk2(gp[(2 * p) * 8 + e], gp[(2 * p + 1) * 8 + e]);
    }

    unsigned long long acc2[2][8];
    unsigned long long den2[2] = {0ull, 0ull};
    #pragma unroll
    for (int p = 0; p < 2; p++)
        #pragma unroll
        for (int e = 0; e < 8; e++) acc2[p][e] = 0ull;

    __syncthreads();

    #pragma unroll 4
    for (int k = 0; k < KEYS; k++) {
        const ulonglong2* row = (const ulonglong2*)&sm[k * 32];
        unsigned long long s20 = 0ull, s21 = 0ull;
        #pragma unroll
        for (int j = 0; j < 4; j++) {
            const ulonglong2 fv = row[j];              // (f2j dup, f2j+1 dup)
            s20 = ffma2(fv.x, g2[0][2*j],     s20);
            s21 = ffma2(fv.x, g2[1][2*j],     s21);
            s20 = ffma2(fv.y, g2[0][2*j + 1], s20);
            s21 = ffma2(fv.y, g2[1][2*j + 1], s21);
        }
        float s0, s1, s2, s3;
        upk2(s20, s0, s1); upk2(s21, s2, s3);
        const unsigned long long p20 = pk2(ex2f(s0), ex2f(s1));
        const unsigned long long p21 = pk2(ex2f(s2), ex2f(s3));
        den2[0] = fadd2(den2[0], p20);
        den2[1] = fadd2(den2[1], p21);
        #pragma unroll
        for (int j = 0; j < 4; j++) {
            const ulonglong2 hv = row[4 + j];          // (h2j dup, h2j+1 dup)
            acc2[0][2*j]     = ffma2(hv.x, p20, acc2[0][2*j]);
            acc2[1][2*j]     = ffma2(hv.x, p21, acc2[1][2*j]);
            acc2[0][2*j + 1] = ffma2(hv.y, p20, acc2[0][2*j + 1]);
            acc2[1][2*j + 1] = ffma2(hv.y, p21, acc2[1][2*j + 1]);
        }
    }

    // Write partials (aligned float4 acc, scalar den)
    const size_t base = ((size_t)ks * Bb + b) * Nn;
    #pragma unroll
    for (int p = 0; p < 2; p++) {
        float lo[8], hi[8], dl, dh;
        #pragma unroll
        for (int e = 0; e < 8; e++) upk2(acc2[p][e], lo[e], hi[e]);
        upk2(den2[p], dl, dh);
        const int mA = m0 + 2 * p, mB = mA + 1;
        float4* oA = (float4*)&d_pacc[(base + mA) * 8];
        float4* oB = (float4*)&d_pacc[(base + mB) * 8];
        oA[0] = make_float4(lo[0], lo[1], lo[2], lo[3]);
        oA[1] = make_float4(lo[4], lo[5], lo[6], lo[7]);
        oB[0] = make_float4(hi[0], hi[1], hi[2], hi[3]);
        oB[1] = make_float4(hi[4], hi[5], hi[6], hi[7]);
        d_pden[base + mA] = dl;
        d_pden[base + mB] = dh;
    }
}

// ---------------- Kernel C: combine splits, Wo projection, y -------------
// grid (Nn/128, Bb), block 128.
__global__ __launch_bounds__(128) void out_kernel(
    const float* __restrict__ x,
    const float* __restrict__ Wo, const float* __restrict__ bo,
    const float* __restrict__ gamma, float* __restrict__ out)
{
    __shared__ float vs[8 * 128];
    __shared__ float wos[512], bos[64];
    const int t = threadIdx.x;
    const int b = blockIdx.y;
    const int m = blockIdx.x * 128 + t;

    for (int i = t; i < 512; i += 128) wos[i] = Wo[i];
    if (t < 64) bos[t] = bo[t];

    float acc[8] = {0,0,0,0,0,0,0,0};
    float den = 0.0f;
    #pragma unroll
    for (int s = 0; s < KSPLIT; s++) {
        const size_t base = ((size_t)s * Bb + b) * Nn + m;
        const float4* pp = (const float4*)&d_pacc[base * 8];
        const float4 a0 = pp[0], a1 = pp[1];
        acc[0] += a0.x; acc[1] += a0.y; acc[2] += a0.z; acc[3] += a0.w;
        acc[4] += a1.x; acc[5] += a1.y; acc[6] += a1.z; acc[7] += a1.w;
        den += d_pden[base];
    }
    const float inv = 1.0f / den;
    #pragma unroll
    for (int e = 0; e < 8; e++) vs[e * 128 + t] = acc[e] * inv;
    __syncthreads();

    const float gam = gamma[0];
    #pragma unroll 4
    for (int c = 0; c < 64; c++) {
        float o = bos[c];
        #pragma unroll
        for (int e = 0; e < 8; e++) o = fmaf(wos[c * 8 + e], vs[e * 128 + t], o);
        const size_t idx = ((size_t)b * 64 + c) * Nn + m;
        out[BCN + idx] = o;                    // o
        out[idx]       = fmaf(gam, o, x[idx]); // y = gamma*o + x
    }
    if (b == 0 && m == 0) out[2 * BCN] = gam;  // gamma scalar
}

// ---------------- Launch --------------------------------------------------
extern "C" void kernel_launch(void* const* d_in, const int* in_sizes, int n_in,
                              void* d_out, int out_size)
{
    const float* x     = (const float*)d_in[0];
    const float* Wk    = (const float*)d_in[1];
    const float* bk    = (const float*)d_in[2];
    const float* Wq    = (const float*)d_in[3];
    const float* bq    = (const float*)d_in[4];
    const float* Wv    = (const float*)d_in[5];
    const float* bv    = (const float*)d_in[6];
    const float* Wo    = (const float*)d_in[7];
    const float* bo    = (const float*)d_in[8];
    const float* gamma = (const float*)d_in[9];
    float* out = (float*)d_out;

    proj_kernel<<<dim3(Nn / 128, Bb), 128>>>(x, Wk, bk, Wq, bq, Wv, bv);
    attn_kernel<<<dim3(KSPLIT, Nn / QT_PER_CTA, Bb), 128>>>();
    out_kernel<<<dim3(Nn / 128, Bb), 128>>>(x, Wo, bo, gamma, out);
}